// round 1
// baseline (speedup 1.0000x reference)
// SSMDiagScan_84731114816205 — gated diagonal SSM
//   y = c * scan(aa, b*u_g) + d_eff * u_g,  u_g = u * sigmoid(u @ W^T + gb)
// Pipeline: [GEMM+gate epilogue+colsum partials] -> [d_eff (rank-4)] -> [scan]
// GEMM uses packed fma.rn.f32x2 (sm_100 full-rate fp32 path).

#include <cuda_runtime.h>
#include <cstdint>

static constexpr int Bdim = 8;
static constexpr int Tdim = 2048;
static constexpr int Ddim = 2048;
static constexpr int Mdim = Bdim * Tdim;     // 16384 rows
static constexpr int BM = 128, BN = 128, BK = 16;
static constexpr int TM = 8, TN = 8;
static constexpr int NTHREADS = (BM / TM) * (BN / TN);   // 256
static constexpr int MTILES = Mdim / BM;      // 128

// Scratch (device globals: allocation-free rule)
__device__ float g_ug[(size_t)Bdim * Tdim * Ddim];     // 134 MB
__device__ float g_partials[(size_t)MTILES * Ddim];    // per-(m-tile, col) colsum of u_g
__device__ float g_deff[Bdim * Ddim];

// ---- packed f32x2 helpers -------------------------------------------------
__device__ __forceinline__ unsigned long long pk2(float x) {
    unsigned long long r;
    asm("mov.b64 %0, {%1, %1};" : "=l"(r) : "f"(x));
    return r;
}
__device__ __forceinline__ void fma2(unsigned long long& d,
                                     unsigned long long a,
                                     unsigned long long b) {
    asm("fma.rn.f32x2 %0, %1, %2, %0;" : "+l"(d) : "l"(a), "l"(b));
}
__device__ __forceinline__ float2 upk(unsigned long long v) {
    float2 r;
    asm("mov.b64 {%0, %1}, %2;" : "=f"(r.x), "=f"(r.y) : "l"(v));
    return r;
}

// ---- Kernel 1: C = U * W^T, fused sigmoid gate, write u_g + colsum partials
__global__ __launch_bounds__(NTHREADS, 2)
void gemm_gate_kernel(const float* __restrict__ U,
                      const float* __restrict__ W,
                      const float* __restrict__ gb) {
    __shared__ float As[BK][BM];   // A transposed: As[k][m]
    __shared__ float Bs[BK][BN];   // B transposed: Bs[k][n]
    __shared__ float Cs[BM / TM ? 16 : 16][BN];  // [16][128] colsum partials

    const int tid = threadIdx.x;
    const int bx = blockIdx.x;            // n tile (0..15)
    const int by = blockIdx.y;            // m tile (0..127)
    const int m0 = by * BM, n0 = bx * BN;
    const int lrow = tid >> 2;            // 0..63
    const int lcol = (tid & 3) * 4;       // 0,4,8,12
    const int tm = tid >> 4;              // 0..15
    const int tn = tid & 15;              // 0..15

    unsigned long long acc[TM][TN / 2];
#pragma unroll
    for (int i = 0; i < TM; i++)
#pragma unroll
        for (int j = 0; j < TN / 2; j++) acc[i][j] = 0ull;

    const float* Aptr = U + (size_t)(m0 + lrow) * Ddim + lcol;
    const float* Bptr = W + (size_t)(n0 + lrow) * Ddim + lcol;

    // prefetch tile 0
    float4 pa0 = *(const float4*)(Aptr);
    float4 pa1 = *(const float4*)(Aptr + (size_t)64 * Ddim);
    float4 pb0 = *(const float4*)(Bptr);
    float4 pb1 = *(const float4*)(Bptr + (size_t)64 * Ddim);

#define STORE_SMEM()                                                        \
    do {                                                                    \
        As[lcol + 0][lrow] = pa0.x; As[lcol + 1][lrow] = pa0.y;             \
        As[lcol + 2][lrow] = pa0.z; As[lcol + 3][lrow] = pa0.w;             \
        As[lcol + 0][lrow + 64] = pa1.x; As[lcol + 1][lrow + 64] = pa1.y;   \
        As[lcol + 2][lrow + 64] = pa1.z; As[lcol + 3][lrow + 64] = pa1.w;   \
        Bs[lcol + 0][lrow] = pb0.x; Bs[lcol + 1][lrow] = pb0.y;             \
        Bs[lcol + 2][lrow] = pb0.z; Bs[lcol + 3][lrow] = pb0.w;             \
        Bs[lcol + 0][lrow + 64] = pb1.x; Bs[lcol + 1][lrow + 64] = pb1.y;   \
        Bs[lcol + 2][lrow + 64] = pb1.z; Bs[lcol + 3][lrow + 64] = pb1.w;   \
    } while (0)

#define COMPUTE_TILE()                                                      \
    do {                                                                    \
        _Pragma("unroll")                                                   \
        for (int k = 0; k < BK; k++) {                                      \
            float4 a0 = *(const float4*)&As[k][tm * TM];                    \
            float4 a1 = *(const float4*)&As[k][tm * TM + 4];                \
            const ulonglong2* bp = (const ulonglong2*)&Bs[k][tn * TN];      \
            ulonglong2 bb0 = bp[0];                                         \
            ulonglong2 bb1 = bp[1];                                         \
            unsigned long long av[8] = {pk2(a0.x), pk2(a0.y), pk2(a0.z),    \
                                        pk2(a0.w), pk2(a1.x), pk2(a1.y),    \
                                        pk2(a1.z), pk2(a1.w)};              \
            unsigned long long bw[4] = {bb0.x, bb0.y, bb1.x, bb1.y};        \
            _Pragma("unroll")                                               \
            for (int i = 0; i < 8; i++) {                                   \
                _Pragma("unroll")                                           \
                for (int j = 0; j < 4; j++) fma2(acc[i][j], av[i], bw[j]);  \
            }                                                               \
        }                                                                   \
    } while (0)

    STORE_SMEM();
    __syncthreads();

    for (int kt = 1; kt < Ddim / BK; ++kt) {
        const float* Ap = Aptr + kt * BK;
        const float* Bp = Bptr + kt * BK;
        pa0 = *(const float4*)(Ap);
        pa1 = *(const float4*)(Ap + (size_t)64 * Ddim);
        pb0 = *(const float4*)(Bp);
        pb1 = *(const float4*)(Bp + (size_t)64 * Ddim);
        COMPUTE_TILE();
        __syncthreads();
        STORE_SMEM();
        __syncthreads();
    }
    COMPUTE_TILE();

    // ---- Epilogue: g = sigmoid(logit + gb), u_g = u*g, colsum partials ----
    float gbl[TN];
    {
        const float4* gp = (const float4*)(gb + n0 + tn * TN);
        float4 g0 = gp[0], g1 = gp[1];
        gbl[0] = g0.x; gbl[1] = g0.y; gbl[2] = g0.z; gbl[3] = g0.w;
        gbl[4] = g1.x; gbl[5] = g1.y; gbl[6] = g1.z; gbl[7] = g1.w;
    }
    float colsum[TN];
#pragma unroll
    for (int j = 0; j < TN; j++) colsum[j] = 0.f;

#pragma unroll
    for (int i = 0; i < TM; i++) {
        const size_t m = (size_t)(m0 + tm * TM + i);
        const float4* up = (const float4*)(U + m * Ddim + n0 + tn * TN);
        float4 u0 = up[0], u1 = up[1];
        float uv[8] = {u0.x, u0.y, u0.z, u0.w, u1.x, u1.y, u1.z, u1.w};
        float out[8];
#pragma unroll
        for (int j = 0; j < 4; j++) {
            float2 cpair = upk(acc[i][j]);
            float l0 = cpair.x + gbl[2 * j];
            float l1 = cpair.y + gbl[2 * j + 1];
            float g0 = 1.f / (1.f + __expf(-l0));
            float g1 = 1.f / (1.f + __expf(-l1));
            out[2 * j] = uv[2 * j] * g0;
            out[2 * j + 1] = uv[2 * j + 1] * g1;
            colsum[2 * j] += out[2 * j];
            colsum[2 * j + 1] += out[2 * j + 1];
        }
        float4* op = (float4*)(g_ug + m * Ddim + n0 + tn * TN);
        op[0] = make_float4(out[0], out[1], out[2], out[3]);
        op[1] = make_float4(out[4], out[5], out[6], out[7]);
    }

#pragma unroll
    for (int j = 0; j < TN; j++) Cs[tm][tn * TN + j] = colsum[j];
    __syncthreads();
    if (tid < BN) {
        float s = 0.f;
#pragma unroll
        for (int i = 0; i < 16; i++) s += Cs[i][tid];
        g_partials[(size_t)by * Ddim + n0 + tid] = s;   // deterministic write
    }
#undef STORE_SMEM
#undef COMPUTE_TILE
}

// ---- Kernel 2: d_eff[b,e] = d[e] + ((mean(u_g) @ U_lr) @ V_lr)[e] / R -----
__global__ void deff_kernel(const float* __restrict__ dvec,
                            const float* __restrict__ dlru,   // [D, 4]
                            const float* __restrict__ dlrv) { // [4, D]
    const int b = blockIdx.x;
    const int tid = threadIdx.x;   // 256
    __shared__ float red[4][256];
    float t0 = 0.f, t1 = 0.f, t2 = 0.f, t3 = 0.f;
    for (int e = tid; e < Ddim; e += 256) {
        float s = 0.f;
#pragma unroll
        for (int i = 0; i < 16; i++)
            s += g_partials[(size_t)(b * 16 + i) * Ddim + e];
        float mean = s * (1.0f / Tdim);
        t0 += mean * dlru[e * 4 + 0];
        t1 += mean * dlru[e * 4 + 1];
        t2 += mean * dlru[e * 4 + 2];
        t3 += mean * dlru[e * 4 + 3];
    }
    red[0][tid] = t0; red[1][tid] = t1; red[2][tid] = t2; red[3][tid] = t3;
    __syncthreads();
    for (int off = 128; off > 0; off >>= 1) {
        if (tid < off) {
            red[0][tid] += red[0][tid + off];
            red[1][tid] += red[1][tid + off];
            red[2][tid] += red[2][tid + off];
            red[3][tid] += red[3][tid + off];
        }
        __syncthreads();
    }
    const float r0 = red[0][0], r1 = red[1][0], r2 = red[2][0], r3 = red[3][0];
    for (int e = tid; e < Ddim; e += 256) {
        float v = r0 * dlrv[e] + r1 * dlrv[Ddim + e] +
                  r2 * dlrv[2 * Ddim + e] + r3 * dlrv[3 * Ddim + e];
        g_deff[b * Ddim + e] = dvec[e] + 0.25f * v;
    }
}

// ---- Kernel 3: per-channel scan  s[t]=aa*s[t-1]+b*ug[t];  y=c*s+deff*ug ---
__global__ __launch_bounds__(64)
void scan_kernel(const float* __restrict__ av,
                 const float* __restrict__ bv,
                 const float* __restrict__ cv,
                 float* __restrict__ Y) {
    const int ch = blockIdx.x * 64 + threadIdx.x;   // 0 .. B*D-1
    const int b = ch >> 11;
    const int dd = ch & (Ddim - 1);
    const float aa = tanhf(av[dd]);
    const float bb = bv[dd];
    const float cc = cv[dd];
    const float de = g_deff[ch];
    const float* p = g_ug + (size_t)b * Tdim * Ddim + dd;
    float* q = Y + (size_t)b * Tdim * Ddim + dd;
    float s = 0.f;
    for (int t0 = 0; t0 < Tdim; t0 += 16) {
        float x[16];
#pragma unroll
        for (int j = 0; j < 16; j++) x[j] = p[(size_t)(t0 + j) * Ddim];
#pragma unroll
        for (int j = 0; j < 16; j++) {
            s = fmaf(aa, s, bb * x[j]);
            q[(size_t)(t0 + j) * Ddim] = fmaf(cc, s, de * x[j]);
        }
    }
}

extern "C" void kernel_launch(void* const* d_in, const int* in_sizes, int n_in,
                              void* d_out, int out_size) {
    const float* U    = (const float*)d_in[0];  // [B,T,D]
    const float* av   = (const float*)d_in[1];  // [D]
    const float* bv   = (const float*)d_in[2];  // [D]
    const float* cv   = (const float*)d_in[3];  // [D]
    const float* dv   = (const float*)d_in[4];  // [D]
    const float* gw   = (const float*)d_in[5];  // [D,D]
    const float* gbp  = (const float*)d_in[6];  // [D]
    const float* dlru = (const float*)d_in[7];  // [D,4]
    const float* dlrv = (const float*)d_in[8];  // [4,D]
    float* Y = (float*)d_out;

    dim3 grid(Ddim / BN, Mdim / BM);            // (16, 128)
    gemm_gate_kernel<<<grid, NTHREADS>>>(U, gw, gbp);
    deff_kernel<<<Bdim, 256>>>(dv, dlru, dlrv);
    scan_kernel<<<(Bdim * Ddim) / 64, 64>>>(av, bv, cv, Y);
}

// round 4
// speedup vs baseline: 2.9341x; 2.9341x over previous
// SSMDiagScan_84731114816205 — gated diagonal SSM
//   y = c * scan(aa, b*u_g) + d_eff * u_g,  u_g = u * sigmoid(u @ W^T + gb)
// K1: tf32 mma.sync (m16n8k8) GEMM, 128x128x32 tiles, 2-stage cp.async,
//     fused sigmoid/u_g epilogue + deterministic colsum partials.
//     (tcgen05 unavailable: harness targets base sm_100, not sm_100a.)
// K2: rank-4 d_eff    K3: per-channel serial scan

#include <cuda_runtime.h>
#include <cstdint>

static constexpr int Bdim = 8;
static constexpr int Tdim = 2048;
static constexpr int Ddim = 2048;
static constexpr int Mdim = Bdim * Tdim;          // 16384
static constexpr int BM = 128, BN = 128, BK = 32;
static constexpr int KTILES = Ddim / BK;          // 64
static constexpr int MTILES = Mdim / BM;          // 128
static constexpr int NTILES = Ddim / BN;          // 16
static constexpr int PITCH = 36;                  // floats per smem row (bank-safe)
static constexpr int TILE_FLOATS = BM * PITCH;    // 4608 (A or B tile)
static constexpr int STAGE_FLOATS = 2 * TILE_FLOATS;
static constexpr int DYN_BYTES = 2 * STAGE_FLOATS * 4;   // 73728

// Scratch (device globals: allocation-free rule)
__device__ float g_ug[(size_t)Bdim * Tdim * Ddim];   // 134 MB
__device__ float g_partials[(size_t)MTILES * Ddim];
__device__ float g_deff[Bdim * Ddim];

// ---------------- helpers ----------------
__device__ __forceinline__ uint32_t cvta_shared(const void* p) {
    uint32_t a;
    asm("{ .reg .u64 t; cvta.to.shared.u64 t, %1; cvt.u32.u64 %0, t; }"
        : "=r"(a) : "l"(p));
    return a;
}
__device__ __forceinline__ void cp_async16(uint32_t saddr, const void* gaddr) {
    asm volatile("cp.async.cg.shared.global [%0], [%1], 16;"
                 :: "r"(saddr), "l"(gaddr) : "memory");
}
__device__ __forceinline__ void cp_commit() {
    asm volatile("cp.async.commit_group;" ::: "memory");
}
template <int N>
__device__ __forceinline__ void cp_wait() {
    asm volatile("cp.async.wait_group %0;" :: "n"(N) : "memory");
}
__device__ __forceinline__ uint32_t f2tf32(float x) {
    uint32_t r;
    asm("cvt.rna.tf32.f32 %0, %1;" : "=r"(r) : "f"(x));
    return r;
}
__device__ __forceinline__ void mma_tf32(float& d0, float& d1, float& d2, float& d3,
                                         uint32_t a0, uint32_t a1, uint32_t a2,
                                         uint32_t a3, uint32_t b0, uint32_t b1) {
    asm volatile(
        "mma.sync.aligned.m16n8k8.row.col.f32.tf32.tf32.f32 "
        "{%0,%1,%2,%3}, {%4,%5,%6,%7}, {%8,%9}, {%0,%1,%2,%3};"
        : "+f"(d0), "+f"(d1), "+f"(d2), "+f"(d3)
        : "r"(a0), "r"(a1), "r"(a2), "r"(a3), "r"(b0), "r"(b1));
}

// ================= Kernel 1: tf32 mma.sync GEMM + gate epilogue =============
__global__ __launch_bounds__(256, 2)
void gemm_gate_mma(const float* __restrict__ U,
                   const float* __restrict__ W,
                   const float* __restrict__ gb) {
    extern __shared__ float sm[];
    __shared__ float s_gb[BN];
    __shared__ float s_red[2][BN];

    const int tid = threadIdx.x;
    const int wid = tid >> 5;
    const int lane = tid & 31;
    const int g = lane >> 2;        // octet row (0..7)
    const int t = lane & 3;         // thread-in-group (0..3)
    const int warp_m = wid >> 2;    // 0..1  (64-row slabs)
    const int warp_n = wid & 3;     // 0..3  (32-col slabs)
    const int n0 = blockIdx.x * BN;
    const int m0 = blockIdx.y * BM;
    const uint32_t smem_base = cvta_shared(sm);

    for (int i = tid; i < BN; i += 256) s_gb[i] = gb[n0 + i];

    float acc[4][4][4];             // [m16 tile][n8 tile][c0..c3]
#pragma unroll
    for (int i = 0; i < 4; i++)
#pragma unroll
        for (int j = 0; j < 4; j++)
#pragma unroll
            for (int r = 0; r < 4; r++) acc[i][j][r] = 0.f;

    // ---- async tile loader: A rows from U, B rows from W, pitch-36 smem ----
    auto load_tile = [&](int kt, int s) {
        const uint32_t ab = smem_base + (uint32_t)(s * STAGE_FLOATS) * 4;
        const uint32_t bb = ab + (uint32_t)TILE_FLOATS * 4;
        const float* gA = U + (size_t)m0 * Ddim + kt * BK;
        const float* gB = W + (size_t)n0 * Ddim + kt * BK;
#pragma unroll
        for (int i = 0; i < 4; i++) {
            const int id = tid + i * 256;
            const int row = id >> 3, c = id & 7;
            cp_async16(ab + (uint32_t)(row * PITCH + c * 4) * 4,
                       gA + (size_t)row * Ddim + c * 4);
        }
#pragma unroll
        for (int i = 0; i < 4; i++) {
            const int id = tid + i * 256;
            const int row = id >> 3, c = id & 7;
            cp_async16(bb + (uint32_t)(row * PITCH + c * 4) * 4,
                       gB + (size_t)row * Ddim + c * 4);
        }
    };

    auto compute_tile = [&](int s) {
        const float* As = sm + s * STAGE_FLOATS;
        const float* Bs = As + TILE_FLOATS;
#pragma unroll
        for (int kk = 0; kk < 4; kk++) {
            const int kb = kk * 8;
            uint32_t a[4][4], b[4][2];
#pragma unroll
            for (int i = 0; i < 4; i++) {
                const int mb = warp_m * 64 + i * 16;
                a[i][0] = f2tf32(As[(mb + g) * PITCH + kb + t]);
                a[i][1] = f2tf32(As[(mb + g + 8) * PITCH + kb + t]);
                a[i][2] = f2tf32(As[(mb + g) * PITCH + kb + t + 4]);
                a[i][3] = f2tf32(As[(mb + g + 8) * PITCH + kb + t + 4]);
            }
#pragma unroll
            for (int j = 0; j < 4; j++) {
                const int nb = warp_n * 32 + j * 8;
                b[j][0] = f2tf32(Bs[(nb + g) * PITCH + kb + t]);
                b[j][1] = f2tf32(Bs[(nb + g) * PITCH + kb + t + 4]);
            }
#pragma unroll
            for (int i = 0; i < 4; i++)
#pragma unroll
                for (int j = 0; j < 4; j++)
                    mma_tf32(acc[i][j][0], acc[i][j][1], acc[i][j][2], acc[i][j][3],
                             a[i][0], a[i][1], a[i][2], a[i][3], b[j][0], b[j][1]);
        }
    };

    // ---- 2-stage pipeline ----
    load_tile(0, 0);
    cp_commit();
#pragma unroll 1
    for (int kt = 0; kt < KTILES; ++kt) {
        if (kt < KTILES - 1) {
            load_tile(kt + 1, (kt + 1) & 1);
            cp_commit();
            cp_wait<1>();
        } else {
            cp_wait<0>();
        }
        __syncthreads();
        compute_tile(kt & 1);
        __syncthreads();
    }

    // ---- epilogue: sigmoid gate, u_g, colsum partials (register-resident) ----
    float csum[4][2];
#pragma unroll
    for (int j = 0; j < 4; j++) { csum[j][0] = 0.f; csum[j][1] = 0.f; }

#pragma unroll
    for (int j = 0; j < 4; j++) {
        const int col = warp_n * 32 + j * 8 + 2 * t;
        const float gb0 = s_gb[col];
        const float gb1 = s_gb[col + 1];
#pragma unroll
        for (int i = 0; i < 4; i++) {
#pragma unroll
            for (int h = 0; h < 2; h++) {
                const int row = warp_m * 64 + i * 16 + h * 8 + g;
                const size_t off = (size_t)(m0 + row) * Ddim + n0 + col;
                const float2 uu = *(const float2*)(U + off);
                const float l0 = acc[i][j][h * 2 + 0] + gb0;
                const float l1 = acc[i][j][h * 2 + 1] + gb1;
                const float ug0 = uu.x * (1.f / (1.f + __expf(-l0)));
                const float ug1 = uu.y * (1.f / (1.f + __expf(-l1)));
                *(float2*)(g_ug + off) = make_float2(ug0, ug1);
                csum[j][0] += ug0;
                csum[j][1] += ug1;
            }
        }
    }
    // reduce over g (lane bits 2..4) via xor-shfl
#pragma unroll
    for (int j = 0; j < 4; j++) {
#pragma unroll
        for (int mask = 16; mask >= 4; mask >>= 1) {
            csum[j][0] += __shfl_xor_sync(0xffffffffu, csum[j][0], mask);
            csum[j][1] += __shfl_xor_sync(0xffffffffu, csum[j][1], mask);
        }
    }
    if (g == 0) {
#pragma unroll
        for (int j = 0; j < 4; j++) {
            s_red[warp_m][warp_n * 32 + j * 8 + 2 * t] = csum[j][0];
            s_red[warp_m][warp_n * 32 + j * 8 + 2 * t + 1] = csum[j][1];
        }
    }
    __syncthreads();
    if (tid < BN)
        g_partials[(size_t)blockIdx.y * Ddim + n0 + tid] =
            s_red[0][tid] + s_red[1][tid];
}

// ======== Kernel 2: d_eff[b,e] = d[e] + ((mean(u_g) @ U_lr) @ V_lr)[e]/R ====
__global__ void deff_kernel(const float* __restrict__ dvec,
                            const float* __restrict__ dlru,   // [D, 4]
                            const float* __restrict__ dlrv) { // [4, D]
    const int b = blockIdx.x;
    const int tid = threadIdx.x;   // 256
    __shared__ float red[4][256];
    float t0 = 0.f, t1 = 0.f, t2 = 0.f, t3 = 0.f;
    for (int e = tid; e < Ddim; e += 256) {
        float s = 0.f;
#pragma unroll
        for (int i = 0; i < 16; i++)
            s += g_partials[(size_t)(b * 16 + i) * Ddim + e];
        float mean = s * (1.0f / Tdim);
        t0 += mean * dlru[e * 4 + 0];
        t1 += mean * dlru[e * 4 + 1];
        t2 += mean * dlru[e * 4 + 2];
        t3 += mean * dlru[e * 4 + 3];
    }
    red[0][tid] = t0; red[1][tid] = t1; red[2][tid] = t2; red[3][tid] = t3;
    __syncthreads();
    for (int off = 128; off > 0; off >>= 1) {
        if (tid < off) {
            red[0][tid] += red[0][tid + off];
            red[1][tid] += red[1][tid + off];
            red[2][tid] += red[2][tid + off];
            red[3][tid] += red[3][tid + off];
        }
        __syncthreads();
    }
    const float r0 = red[0][0], r1 = red[1][0], r2 = red[2][0], r3 = red[3][0];
    for (int e = tid; e < Ddim; e += 256) {
        float v = r0 * dlrv[e] + r1 * dlrv[Ddim + e] +
                  r2 * dlrv[2 * Ddim + e] + r3 * dlrv[3 * Ddim + e];
        g_deff[b * Ddim + e] = dvec[e] + 0.25f * v;
    }
}

// ==== Kernel 3: per-channel scan  s[t]=aa*s[t-1]+b*ug[t];  y=c*s+deff*ug ====
__global__ __launch_bounds__(64)
void scan_kernel(const float* __restrict__ av,
                 const float* __restrict__ bv,
                 const float* __restrict__ cv,
                 float* __restrict__ Y) {
    const int ch = blockIdx.x * 64 + threadIdx.x;   // 0 .. B*D-1
    const int b = ch >> 11;
    const int dd = ch & (Ddim - 1);
    const float aa = tanhf(av[dd]);
    const float bb = bv[dd];
    const float cc = cv[dd];
    const float de = g_deff[ch];
    const float* p = g_ug + (size_t)b * Tdim * Ddim + dd;
    float* q = Y + (size_t)b * Tdim * Ddim + dd;
    float s = 0.f;
    for (int t0 = 0; t0 < Tdim; t0 += 16) {
        float x[16];
#pragma unroll
        for (int j = 0; j < 16; j++) x[j] = p[(size_t)(t0 + j) * Ddim];
#pragma unroll
        for (int j = 0; j < 16; j++) {
            s = fmaf(aa, s, bb * x[j]);
            q[(size_t)(t0 + j) * Ddim] = fmaf(cc, s, de * x[j]);
        }
    }
}

extern "C" void kernel_launch(void* const* d_in, const int* in_sizes, int n_in,
                              void* d_out, int out_size) {
    const float* U    = (const float*)d_in[0];  // [B,T,D]
    const float* av   = (const float*)d_in[1];  // [D]
    const float* bv   = (const float*)d_in[2];  // [D]
    const float* cv   = (const float*)d_in[3];  // [D]
    const float* dv   = (const float*)d_in[4];  // [D]
    const float* gw   = (const float*)d_in[5];  // [D,D]
    const float* gbp  = (const float*)d_in[6];  // [D]
    const float* dlru = (const float*)d_in[7];  // [D,4]
    const float* dlrv = (const float*)d_in[8];  // [4,D]
    float* Y = (float*)d_out;

    cudaFuncSetAttribute(gemm_gate_mma,
                         cudaFuncAttributeMaxDynamicSharedMemorySize, DYN_BYTES);
    gemm_gate_mma<<<dim3(NTILES, MTILES), 256, DYN_BYTES>>>(U, gw, gbp);
    deff_kernel<<<Bdim, 256>>>(dv, dlru, dlrv);
    scan_kernel<<<(Bdim * Ddim) / 64, 64>>>(av, bv, cv, Y);
}

// round 6
// speedup vs baseline: 5.9463x; 2.0266x over previous
// SSMDiagScan_84731114816205 — gated diagonal SSM
//   y = c * scan(aa, b*u_g) + d_eff * u_g,  u_g = u * sigmoid(u @ W^T + gb)
// K0: fp32->fp16 pre-convert of U and W (once per launch, ~16us)
// K1: fp16 mma.sync m16n8k16 (fp32 accum) GEMM, 128x128x64 tiles, 2-stage
//     cp.async, ldmatrix fragment loads, fused sigmoid/u_g epilogue +
//     deterministic colsum partials. (tcgen05 unavailable: base sm_100 target.)
// K2: rank-4 d_eff    K3: per-channel serial scan

#include <cuda_runtime.h>
#include <cuda_fp16.h>
#include <cstdint>

static constexpr int Bdim = 8;
static constexpr int Tdim = 2048;
static constexpr int Ddim = 2048;
static constexpr int Mdim = Bdim * Tdim;          // 16384
static constexpr int BM = 128, BN = 128, BK = 64;
static constexpr int KTILES = Ddim / BK;          // 32
static constexpr int MTILES = Mdim / BM;          // 128
static constexpr int NTILES = Ddim / BN;          // 16
static constexpr int A_TILE_BYTES = BM * BK * 2;  // 16384
static constexpr int STAGE_BYTES = 2 * A_TILE_BYTES;      // 32768 (A+B)
static constexpr int DYN_BYTES = 2 * STAGE_BYTES;         // 65536

// Scratch (device globals: allocation-free rule)
__device__ float  g_ug[(size_t)Bdim * Tdim * Ddim];   // 134 MB
__device__ __half g_uh[(size_t)Mdim * Ddim];          // 64 MB
__device__ __half g_wh[(size_t)Ddim * Ddim];          // 8 MB
__device__ float  g_partials[(size_t)MTILES * Ddim];
__device__ float  g_deff[Bdim * Ddim];

// ---------------- helpers ----------------
__device__ __forceinline__ uint32_t cvta_shared(const void* p) {
    uint32_t a;
    asm("{ .reg .u64 t; cvta.to.shared.u64 t, %1; cvt.u32.u64 %0, t; }"
        : "=r"(a) : "l"(p));
    return a;
}
__device__ __forceinline__ void cp_async16(uint32_t saddr, const void* gaddr) {
    asm volatile("cp.async.cg.shared.global [%0], [%1], 16;"
                 :: "r"(saddr), "l"(gaddr) : "memory");
}
__device__ __forceinline__ void cp_commit() {
    asm volatile("cp.async.commit_group;" ::: "memory");
}
template <int N>
__device__ __forceinline__ void cp_wait() {
    asm volatile("cp.async.wait_group %0;" :: "n"(N) : "memory");
}
__device__ __forceinline__ uint32_t sw128(uint32_t off) {
    return off ^ ((off >> 3) & 0x70);
}
__device__ __forceinline__ void ldsm_x4(uint32_t* r, uint32_t addr) {
    asm volatile("ldmatrix.sync.aligned.m8n8.x4.shared.b16 {%0,%1,%2,%3}, [%4];"
                 : "=r"(r[0]), "=r"(r[1]), "=r"(r[2]), "=r"(r[3]) : "r"(addr));
}
__device__ __forceinline__ void mma_f16(float& d0, float& d1, float& d2, float& d3,
                                        uint32_t a0, uint32_t a1, uint32_t a2,
                                        uint32_t a3, uint32_t b0, uint32_t b1) {
    asm volatile(
        "mma.sync.aligned.m16n8k16.row.col.f32.f16.f16.f32 "
        "{%0,%1,%2,%3}, {%4,%5,%6,%7}, {%8,%9}, {%0,%1,%2,%3};"
        : "+f"(d0), "+f"(d1), "+f"(d2), "+f"(d3)
        : "r"(a0), "r"(a1), "r"(a2), "r"(a3), "r"(b0), "r"(b1));
}

// ============ Kernel 0: fp32 -> fp16 convert (vectorized) ============
__global__ __launch_bounds__(256)
void conv_half(const float* __restrict__ src, __half* __restrict__ dst) {
    const size_t i = (size_t)blockIdx.x * 256 + threadIdx.x;
    float4 v = ((const float4*)src)[i];
    __half2 h0 = __floats2half2_rn(v.x, v.y);
    __half2 h1 = __floats2half2_rn(v.z, v.w);
    ((__half2*)dst)[2 * i] = h0;
    ((__half2*)dst)[2 * i + 1] = h1;
}

// ======= Kernel 1: fp16 mma.sync GEMM (fp32 accum) + gate epilogue =======
__global__ __launch_bounds__(256, 2)
void gemm_gate_mma(const float* __restrict__ U,
                   const float* __restrict__ gb) {
    extern __shared__ __align__(128) char sm[];
    __shared__ float s_gb[BN];
    __shared__ float s_red[2][BN];

    const int tid = threadIdx.x;
    const int wid = tid >> 5;
    const int lane = tid & 31;
    const int g = lane >> 2;        // octet row (0..7)
    const int t = lane & 3;         // thread-in-group (0..3)
    const int grp = lane >> 3;      // ldmatrix address group (0..3)
    const int lrow = lane & 7;
    const int warp_m = wid >> 2;    // 0..1  (64-row slabs)
    const int warp_n = wid & 3;     // 0..3  (32-col slabs)
    const int n0 = blockIdx.x * BN;
    const int m0 = blockIdx.y * BM;
    const uint32_t smem_base = cvta_shared(sm);

    // ldmatrix per-lane sub-offsets (within a 16-row / 32-byte k block):
    //  A x4 regs: [m0-7,k0-7],[m8-15,k0-7],[m0-7,k8-15],[m8-15,k8-15]
    const int rowoff_a = ((grp & 1) << 3) + lrow;
    const int koff_a = (grp >> 1) << 4;
    //  B x4 regs: [n0-7,k0-7],[n0-7,k8-15],[n8-15,k0-7],[n8-15,k8-15]
    const int rowoff_b = ((grp >> 1) << 3) + lrow;
    const int koff_b = (grp & 1) << 4;

    for (int i = tid; i < BN; i += 256) s_gb[i] = gb[n0 + i];

    float acc[4][4][4];             // [m16 tile][n8 tile][c0..c3]
#pragma unroll
    for (int i = 0; i < 4; i++)
#pragma unroll
        for (int j = 0; j < 4; j++)
#pragma unroll
            for (int r = 0; r < 4; r++) acc[i][j][r] = 0.f;

    // ---- async tile loader: fp16 A rows from g_uh, B rows from g_wh ----
    // tile row = 64 halves = 128 bytes = 8 x 16B chunks (SW128 swizzled)
    auto load_tile = [&](int kt, int s) {
        const uint32_t ab = smem_base + (uint32_t)s * STAGE_BYTES;
        const uint32_t bb = ab + A_TILE_BYTES;
        const __half* gA = g_uh + (size_t)m0 * Ddim + kt * BK;
        const __half* gB = g_wh + (size_t)n0 * Ddim + kt * BK;
#pragma unroll
        for (int i = 0; i < 4; i++) {
            const int id = tid + i * 256;
            const int row = id >> 3, c = id & 7;
            cp_async16(ab + sw128((uint32_t)(row * 128 + c * 16)),
                       gA + (size_t)row * Ddim + c * 8);
        }
#pragma unroll
        for (int i = 0; i < 4; i++) {
            const int id = tid + i * 256;
            const int row = id >> 3, c = id & 7;
            cp_async16(bb + sw128((uint32_t)(row * 128 + c * 16)),
                       gB + (size_t)row * Ddim + c * 8);
        }
    };

    auto compute_tile = [&](int st) {
        const uint32_t ab = smem_base + (uint32_t)st * STAGE_BYTES;
        const uint32_t bb = ab + A_TILE_BYTES;
#pragma unroll
        for (int s = 0; s < BK / 16; s++) {          // 4 k-steps of 16
            uint32_t a[4][4], b[2][4];
#pragma unroll
            for (int i = 0; i < 4; i++) {
                const int row = warp_m * 64 + i * 16 + rowoff_a;
                ldsm_x4(a[i], ab + sw128((uint32_t)(row * 128 + s * 32 + koff_a)));
            }
#pragma unroll
            for (int jj = 0; jj < 2; jj++) {
                const int row = warp_n * 32 + jj * 16 + rowoff_b;
                ldsm_x4(b[jj], bb + sw128((uint32_t)(row * 128 + s * 32 + koff_b)));
            }
#pragma unroll
            for (int i = 0; i < 4; i++)
#pragma unroll
                for (int j = 0; j < 4; j++)
                    mma_f16(acc[i][j][0], acc[i][j][1], acc[i][j][2], acc[i][j][3],
                            a[i][0], a[i][1], a[i][2], a[i][3],
                            b[j >> 1][(j & 1) * 2 + 0], b[j >> 1][(j & 1) * 2 + 1]);
        }
    };

    // ---- 2-stage pipeline ----
    load_tile(0, 0);
    cp_commit();
#pragma unroll 1
    for (int kt = 0; kt < KTILES; ++kt) {
        if (kt < KTILES - 1) {
            load_tile(kt + 1, (kt + 1) & 1);
            cp_commit();
            cp_wait<1>();
        } else {
            cp_wait<0>();
        }
        __syncthreads();
        compute_tile(kt & 1);
        __syncthreads();
    }

    // ---- epilogue: sigmoid gate, u_g, colsum partials (register-resident) ----
    float csum[4][2];
#pragma unroll
    for (int j = 0; j < 4; j++) { csum[j][0] = 0.f; csum[j][1] = 0.f; }

#pragma unroll
    for (int j = 0; j < 4; j++) {
        const int col = warp_n * 32 + j * 8 + 2 * t;
        const float gb0 = s_gb[col];
        const float gb1 = s_gb[col + 1];
#pragma unroll
        for (int i = 0; i < 4; i++) {
#pragma unroll
            for (int h = 0; h < 2; h++) {
                const int row = warp_m * 64 + i * 16 + h * 8 + g;
                const size_t off = (size_t)(m0 + row) * Ddim + n0 + col;
                const float2 uu = *(const float2*)(U + off);
                const float l0 = acc[i][j][h * 2 + 0] + gb0;
                const float l1 = acc[i][j][h * 2 + 1] + gb1;
                const float ug0 = uu.x * (1.f / (1.f + __expf(-l0)));
                const float ug1 = uu.y * (1.f / (1.f + __expf(-l1)));
                *(float2*)(g_ug + off) = make_float2(ug0, ug1);
                csum[j][0] += ug0;
                csum[j][1] += ug1;
            }
        }
    }
    // reduce over g (lane bits 2..4) via xor-shfl
#pragma unroll
    for (int j = 0; j < 4; j++) {
#pragma unroll
        for (int mask = 16; mask >= 4; mask >>= 1) {
            csum[j][0] += __shfl_xor_sync(0xffffffffu, csum[j][0], mask);
            csum[j][1] += __shfl_xor_sync(0xffffffffu, csum[j][1], mask);
        }
    }
    if (g == 0) {
#pragma unroll
        for (int j = 0; j < 4; j++) {
            s_red[warp_m][warp_n * 32 + j * 8 + 2 * t] = csum[j][0];
            s_red[warp_m][warp_n * 32 + j * 8 + 2 * t + 1] = csum[j][1];
        }
    }
    __syncthreads();
    if (tid < BN)
        g_partials[(size_t)blockIdx.y * Ddim + n0 + tid] =
            s_red[0][tid] + s_red[1][tid];
}

// ======== Kernel 2: d_eff[b,e] = d[e] + ((mean(u_g) @ U_lr) @ V_lr)[e]/R ====
__global__ void deff_kernel(const float* __restrict__ dvec,
                            const float* __restrict__ dlru,   // [D, 4]
                            const float* __restrict__ dlrv) { // [4, D]
    const int b = blockIdx.x;
    const int tid = threadIdx.x;   // 256
    __shared__ float red[4][256];
    float t0 = 0.f, t1 = 0.f, t2 = 0.f, t3 = 0.f;
    for (int e = tid; e < Ddim; e += 256) {
        float s = 0.f;
#pragma unroll
        for (int i = 0; i < 16; i++)
            s += g_partials[(size_t)(b * 16 + i) * Ddim + e];
        float mean = s * (1.0f / Tdim);
        t0 += mean * dlru[e * 4 + 0];
        t1 += mean * dlru[e * 4 + 1];
        t2 += mean * dlru[e * 4 + 2];
        t3 += mean * dlru[e * 4 + 3];
    }
    red[0][tid] = t0; red[1][tid] = t1; red[2][tid] = t2; red[3][tid] = t3;
    __syncthreads();
    for (int off = 128; off > 0; off >>= 1) {
        if (tid < off) {
            red[0][tid] += red[0][tid + off];
            red[1][tid] += red[1][tid + off];
            red[2][tid] += red[2][tid + off];
            red[3][tid] += red[3][tid + off];
        }
        __syncthreads();
    }
    const float r0 = red[0][0], r1 = red[1][0], r2 = red[2][0], r3 = red[3][0];
    for (int e = tid; e < Ddim; e += 256) {
        float v = r0 * dlrv[e] + r1 * dlrv[Ddim + e] +
                  r2 * dlrv[2 * Ddim + e] + r3 * dlrv[3 * Ddim + e];
        g_deff[b * Ddim + e] = dvec[e] + 0.25f * v;
    }
}

// ==== Kernel 3: per-channel scan  s[t]=aa*s[t-1]+b*ug[t];  y=c*s+deff*ug ====
__global__ __launch_bounds__(64)
void scan_kernel(const float* __restrict__ av,
                 const float* __restrict__ bv,
                 const float* __restrict__ cv,
                 float* __restrict__ Y) {
    const int ch = blockIdx.x * 64 + threadIdx.x;   // 0 .. B*D-1
    const int b = ch >> 11;
    const int dd = ch & (Ddim - 1);
    const float aa = tanhf(av[dd]);
    const float bb = bv[dd];
    const float cc = cv[dd];
    const float de = g_deff[ch];
    const float* p = g_ug + (size_t)b * Tdim * Ddim + dd;
    float* q = Y + (size_t)b * Tdim * Ddim + dd;
    float s = 0.f;
    for (int t0 = 0; t0 < Tdim; t0 += 32) {
        float x[32];
#pragma unroll
        for (int j = 0; j < 32; j++) x[j] = p[(size_t)(t0 + j) * Ddim];
#pragma unroll
        for (int j = 0; j < 32; j++) {
            s = fmaf(aa, s, bb * x[j]);
            q[(size_t)(t0 + j) * Ddim] = fmaf(cc, s, de * x[j]);
        }
    }
}

extern "C" void kernel_launch(void* const* d_in, const int* in_sizes, int n_in,
                              void* d_out, int out_size) {
    const float* U    = (const float*)d_in[0];  // [B,T,D]
    const float* av   = (const float*)d_in[1];  // [D]
    const float* bv   = (const float*)d_in[2];  // [D]
    const float* cv   = (const float*)d_in[3];  // [D]
    const float* dv   = (const float*)d_in[4];  // [D]
    const float* gw   = (const float*)d_in[5];  // [D,D]
    const float* gbp  = (const float*)d_in[6];  // [D]
    const float* dlru = (const float*)d_in[7];  // [D,4]
    const float* dlrv = (const float*)d_in[8];  // [4,D]
    float* Y = (float*)d_out;

    __half* uh_p; cudaGetSymbolAddress((void**)&uh_p, g_uh);
    __half* wh_p; cudaGetSymbolAddress((void**)&wh_p, g_wh);

    // K0: pre-convert U (8M float4) and W (1M float4) to fp16
    conv_half<<<(Mdim * (size_t)Ddim / 4) / 256, 256>>>(U, uh_p);
    conv_half<<<((size_t)Ddim * Ddim / 4) / 256, 256>>>(gw, wh_p);

    cudaFuncSetAttribute(gemm_gate_mma,
                         cudaFuncAttributeMaxDynamicSharedMemorySize, DYN_BYTES);
    gemm_gate_mma<<<dim3(NTILES, MTILES), 256, DYN_BYTES>>>(U, gbp);
    deff_kernel<<<Bdim, 256>>>(dv, dlru, dlrv);
    scan_kernel<<<(Bdim * Ddim) / 64, 64>>>(av, bv, cv, Y);
}

// round 8
// speedup vs baseline: 5.9764x; 1.0051x over previous
// SSMDiagScan_84731114816205 — gated diagonal SSM
//   y = c * scan(aa, b*u_g) + d_eff * u_g,  u_g = u * sigmoid(u @ W^T + gb)
// K0: fp32->fp16 pre-convert of U and W
// K1: fp16 mma.sync m16n8k16 (fp32 accum) GEMM, 128x128x64 tiles, 3-stage
//     cp.async (1 sync/iter), ldmatrix, fused sigmoid/u_g epilogue (fp16 u_g
//     out) + deterministic colsum partials.
// K2: r[b][4] reduction    K3: per-channel scan with inline d_eff

#include <cuda_runtime.h>
#include <cuda_fp16.h>
#include <cstdint>

static constexpr int Bdim = 8;
static constexpr int Tdim = 2048;
static constexpr int Ddim = 2048;
static constexpr int Mdim = Bdim * Tdim;          // 16384
static constexpr int BM = 128, BN = 128, BK = 64;
static constexpr int KTILES = Ddim / BK;          // 32
static constexpr int MTILES = Mdim / BM;          // 128
static constexpr int NTILES = Ddim / BN;          // 16
static constexpr int STAGES = 3;
static constexpr int A_TILE_BYTES = BM * BK * 2;  // 16384
static constexpr int STAGE_BYTES = 2 * A_TILE_BYTES;      // 32768 (A+B)
static constexpr int DYN_BYTES = STAGES * STAGE_BYTES;    // 98304

// Scratch (device globals: allocation-free rule)
__device__ __half g_ugh[(size_t)Mdim * Ddim];         // 64 MB (u_g fp16)
__device__ __half g_uh[(size_t)Mdim * Ddim];          // 64 MB
__device__ __half g_wh[(size_t)Ddim * Ddim];          // 8 MB
__device__ float  g_partials[(size_t)MTILES * Ddim];
__device__ float  g_r[Bdim * 4];

// ---------------- helpers ----------------
__device__ __forceinline__ uint32_t cvta_shared(const void* p) {
    uint32_t a;
    asm("{ .reg .u64 t; cvta.to.shared.u64 t, %1; cvt.u32.u64 %0, t; }"
        : "=r"(a) : "l"(p));
    return a;
}
__device__ __forceinline__ void cp_async16(uint32_t saddr, const void* gaddr) {
    asm volatile("cp.async.cg.shared.global [%0], [%1], 16;"
                 :: "r"(saddr), "l"(gaddr) : "memory");
}
__device__ __forceinline__ void cp_commit() {
    asm volatile("cp.async.commit_group;" ::: "memory");
}
template <int N>
__device__ __forceinline__ void cp_wait() {
    asm volatile("cp.async.wait_group %0;" :: "n"(N) : "memory");
}
__device__ __forceinline__ uint32_t sw128(uint32_t off) {
    return off ^ ((off >> 3) & 0x70);
}
__device__ __forceinline__ void ldsm_x4(uint32_t* r, uint32_t addr) {
    asm volatile("ldmatrix.sync.aligned.m8n8.x4.shared.b16 {%0,%1,%2,%3}, [%4];"
                 : "=r"(r[0]), "=r"(r[1]), "=r"(r[2]), "=r"(r[3]) : "r"(addr));
}
__device__ __forceinline__ void mma_f16(float& d0, float& d1, float& d2, float& d3,
                                        uint32_t a0, uint32_t a1, uint32_t a2,
                                        uint32_t a3, uint32_t b0, uint32_t b1) {
    asm volatile(
        "mma.sync.aligned.m16n8k16.row.col.f32.f16.f16.f32 "
        "{%0,%1,%2,%3}, {%4,%5,%6,%7}, {%8,%9}, {%0,%1,%2,%3};"
        : "+f"(d0), "+f"(d1), "+f"(d2), "+f"(d3)
        : "r"(a0), "r"(a1), "r"(a2), "r"(a3), "r"(b0), "r"(b1));
}

// ============ Kernel 0: fp32 -> fp16 convert (vectorized) ============
__global__ __launch_bounds__(256)
void conv_half(const float* __restrict__ src, __half* __restrict__ dst) {
    const size_t i = (size_t)blockIdx.x * 256 + threadIdx.x;
    float4 v = ((const float4*)src)[i];
    ((__half2*)dst)[2 * i] = __floats2half2_rn(v.x, v.y);
    ((__half2*)dst)[2 * i + 1] = __floats2half2_rn(v.z, v.w);
}

// ======= Kernel 1: fp16 mma.sync GEMM (fp32 accum) + gate epilogue =======
__global__ __launch_bounds__(256, 2)
void gemm_gate_mma(const float* __restrict__ gb) {
    extern __shared__ __align__(128) char sm[];
    __shared__ float s_gb[BN];
    __shared__ float s_red[2][BN];

    const int tid = threadIdx.x;
    const int wid = tid >> 5;
    const int lane = tid & 31;
    const int g = lane >> 2;        // octet row (0..7)
    const int t = lane & 3;         // thread-in-group (0..3)
    const int grp = lane >> 3;      // ldmatrix address group (0..3)
    const int lrow = lane & 7;
    const int warp_m = wid >> 2;    // 0..1  (64-row slabs)
    const int warp_n = wid & 3;     // 0..3  (32-col slabs)
    const int n0 = blockIdx.x * BN;
    const int m0 = blockIdx.y * BM;
    const uint32_t smem_base = cvta_shared(sm);

    const int rowoff_a = ((grp & 1) << 3) + lrow;
    const int koff_a = (grp >> 1) << 4;
    const int rowoff_b = ((grp >> 1) << 3) + lrow;
    const int koff_b = (grp & 1) << 4;

    for (int i = tid; i < BN; i += 256) s_gb[i] = gb[n0 + i];

    float acc[4][4][4];             // [m16 tile][n8 tile][c0..c3]
#pragma unroll
    for (int i = 0; i < 4; i++)
#pragma unroll
        for (int j = 0; j < 4; j++)
#pragma unroll
            for (int r = 0; r < 4; r++) acc[i][j][r] = 0.f;

    auto load_tile = [&](int kt, int s) {
        const uint32_t ab = smem_base + (uint32_t)s * STAGE_BYTES;
        const uint32_t bb = ab + A_TILE_BYTES;
        const __half* gA = g_uh + (size_t)m0 * Ddim + kt * BK;
        const __half* gB = g_wh + (size_t)n0 * Ddim + kt * BK;
#pragma unroll
        for (int i = 0; i < 4; i++) {
            const int id = tid + i * 256;
            const int row = id >> 3, c = id & 7;
            cp_async16(ab + sw128((uint32_t)(row * 128 + c * 16)),
                       gA + (size_t)row * Ddim + c * 8);
        }
#pragma unroll
        for (int i = 0; i < 4; i++) {
            const int id = tid + i * 256;
            const int row = id >> 3, c = id & 7;
            cp_async16(bb + sw128((uint32_t)(row * 128 + c * 16)),
                       gB + (size_t)row * Ddim + c * 8);
        }
    };

    auto compute_tile = [&](int st) {
        const uint32_t ab = smem_base + (uint32_t)st * STAGE_BYTES;
        const uint32_t bb = ab + A_TILE_BYTES;
#pragma unroll
        for (int s = 0; s < BK / 16; s++) {          // 4 k-steps of 16
            uint32_t a[4][4], b[2][4];
#pragma unroll
            for (int i = 0; i < 4; i++) {
                const int row = warp_m * 64 + i * 16 + rowoff_a;
                ldsm_x4(a[i], ab + sw128((uint32_t)(row * 128 + s * 32 + koff_a)));
            }
#pragma unroll
            for (int jj = 0; jj < 2; jj++) {
                const int row = warp_n * 32 + jj * 16 + rowoff_b;
                ldsm_x4(b[jj], bb + sw128((uint32_t)(row * 128 + s * 32 + koff_b)));
            }
#pragma unroll
            for (int i = 0; i < 4; i++)
#pragma unroll
                for (int j = 0; j < 4; j++)
                    mma_f16(acc[i][j][0], acc[i][j][1], acc[i][j][2], acc[i][j][3],
                            a[i][0], a[i][1], a[i][2], a[i][3],
                            b[j >> 1][(j & 1) * 2 + 0], b[j >> 1][(j & 1) * 2 + 1]);
        }
    };

    // ---- 3-stage pipeline, one syncthreads per iteration ----
    load_tile(0, 0);
    cp_commit();
    load_tile(1, 1);
    cp_commit();
#pragma unroll 1
    for (int kt = 0; kt < KTILES; ++kt) {
        cp_wait<1>();                      // stage kt resident
        __syncthreads();                   // all warps done with stage kt-1
        if (kt + 2 < KTILES) load_tile(kt + 2, (kt + 2) % STAGES);
        cp_commit();
        compute_tile(kt % STAGES);
    }

    // ---- epilogue: sigmoid gate, u_g (fp16 out), colsum partials ----
    float csum[4][2];
#pragma unroll
    for (int j = 0; j < 4; j++) { csum[j][0] = 0.f; csum[j][1] = 0.f; }

#pragma unroll
    for (int j = 0; j < 4; j++) {
        const int col = warp_n * 32 + j * 8 + 2 * t;
        const float gb0 = s_gb[col];
        const float gb1 = s_gb[col + 1];
#pragma unroll
        for (int i = 0; i < 4; i++) {
#pragma unroll
            for (int h = 0; h < 2; h++) {
                const int row = warp_m * 64 + i * 16 + h * 8 + g;
                const size_t off = (size_t)(m0 + row) * Ddim + n0 + col;
                const __half2 uu = *(const __half2*)(g_uh + off);
                const float l0 = acc[i][j][h * 2 + 0] + gb0;
                const float l1 = acc[i][j][h * 2 + 1] + gb1;
                const float ug0 = __half2float(uu.x) * (1.f / (1.f + __expf(-l0)));
                const float ug1 = __half2float(uu.y) * (1.f / (1.f + __expf(-l1)));
                *(__half2*)(g_ugh + off) = __floats2half2_rn(ug0, ug1);
                csum[j][0] += ug0;
                csum[j][1] += ug1;
            }
        }
    }
#pragma unroll
    for (int j = 0; j < 4; j++) {
#pragma unroll
        for (int mask = 16; mask >= 4; mask >>= 1) {
            csum[j][0] += __shfl_xor_sync(0xffffffffu, csum[j][0], mask);
            csum[j][1] += __shfl_xor_sync(0xffffffffu, csum[j][1], mask);
        }
    }
    if (g == 0) {
#pragma unroll
        for (int j = 0; j < 4; j++) {
            s_red[warp_m][warp_n * 32 + j * 8 + 2 * t] = csum[j][0];
            s_red[warp_m][warp_n * 32 + j * 8 + 2 * t + 1] = csum[j][1];
        }
    }
    __syncthreads();
    if (tid < BN)
        g_partials[(size_t)blockIdx.y * Ddim + n0 + tid] =
            s_red[0][tid] + s_red[1][tid];
}

// ==== Kernel 2: r[b][r] = sum_e mean_ug[b][e] * dlru[e][r]  (grid 4 x 8) ====
__global__ __launch_bounds__(256)
void rvec_kernel(const float* __restrict__ dlru) {   // [D, 4]
    const int r = blockIdx.x;        // 0..3
    const int b = blockIdx.y;        // 0..7
    const int tid = threadIdx.x;     // 256
    __shared__ float red[256];
    float acc = 0.f;
    for (int e = tid; e < Ddim; e += 256) {
        float s = 0.f;
#pragma unroll
        for (int i = 0; i < 16; i++)
            s += g_partials[(size_t)(b * 16 + i) * Ddim + e];
        acc += (s * (1.0f / Tdim)) * dlru[e * 4 + r];
    }
    red[tid] = acc;
    __syncthreads();
    for (int off = 128; off > 0; off >>= 1) {
        if (tid < off) red[tid] += red[tid + off];
        __syncthreads();
    }
    if (tid == 0) g_r[b * 4 + r] = red[0];
}

// ==== Kernel 3: per-channel scan with inline d_eff =========================
__global__ __launch_bounds__(64)
void scan_kernel(const float* __restrict__ av,
                 const float* __restrict__ bv,
                 const float* __restrict__ cv,
                 const float* __restrict__ dvec,
                 const float* __restrict__ dlrv,   // [4, D]
                 float* __restrict__ Y) {
    const int ch = blockIdx.x * 64 + threadIdx.x;   // 0 .. B*D-1
    const int b = ch >> 11;
    const int dd = ch & (Ddim - 1);
    const float aa = tanhf(av[dd]);
    const float bb = bv[dd];
    const float cc = cv[dd];
    const float de = dvec[dd] +
        0.25f * (g_r[b * 4 + 0] * dlrv[dd] +
                 g_r[b * 4 + 1] * dlrv[Ddim + dd] +
                 g_r[b * 4 + 2] * dlrv[2 * Ddim + dd] +
                 g_r[b * 4 + 3] * dlrv[3 * Ddim + dd]);
    const __half* p = g_ugh + (size_t)b * Tdim * Ddim + dd;
    float* q = Y + (size_t)b * Tdim * Ddim + dd;
    float s = 0.f;
    for (int t0 = 0; t0 < Tdim; t0 += 32) {
        __half x[32];
#pragma unroll
        for (int j = 0; j < 32; j++) x[j] = p[(size_t)(t0 + j) * Ddim];
#pragma unroll
        for (int j = 0; j < 32; j++) {
            const float xf = __half2float(x[j]);
            s = fmaf(aa, s, bb * xf);
            q[(size_t)(t0 + j) * Ddim] = fmaf(cc, s, de * xf);
        }
    }
}

extern "C" void kernel_launch(void* const* d_in, const int* in_sizes, int n_in,
                              void* d_out, int out_size) {
    const float* U    = (const float*)d_in[0];  // [B,T,D]
    const float* av   = (const float*)d_in[1];  // [D]
    const float* bv   = (const float*)d_in[2];  // [D]
    const float* cv   = (const float*)d_in[3];  // [D]
    const float* dv   = (const float*)d_in[4];  // [D]
    const float* gw   = (const float*)d_in[5];  // [D,D]
    const float* gbp  = (const float*)d_in[6];  // [D]
    const float* dlru = (const float*)d_in[7];  // [D,4]
    const float* dlrv = (const float*)d_in[8];  // [4,D]
    float* Y = (float*)d_out;

    __half* uh_p; cudaGetSymbolAddress((void**)&uh_p, g_uh);
    __half* wh_p; cudaGetSymbolAddress((void**)&wh_p, g_wh);

    conv_half<<<(Mdim * (size_t)Ddim / 4) / 256, 256>>>(U, uh_p);
    conv_half<<<((size_t)Ddim * Ddim / 4) / 256, 256>>>(gw, wh_p);

    cudaFuncSetAttribute(gemm_gate_mma,
                         cudaFuncAttributeMaxDynamicSharedMemorySize, DYN_BYTES);
    gemm_gate_mma<<<dim3(NTILES, MTILES), 256, DYN_BYTES>>>(gbp);
    rvec_kernel<<<dim3(4, Bdim), 256>>>(dlru);
    scan_kernel<<<(Bdim * Ddim) / 64, 64>>>(av, bv, cv, dv, dlrv, Y);
}